// round 1
// baseline (speedup 1.0000x reference)
#include <cuda_runtime.h>
#include <cuda_bf16.h>

#define NNODES 100000
#define INDIM 384
#define HID 256
#define BN_EPS 1e-5f

// ---------------- scratch (allocation-free: device globals) ----------------
__device__ float g_bufA[(size_t)NNODES * HID];   // 102.4 MB
__device__ float g_bufB[(size_t)NNODES * HID];   // 102.4 MB
__device__ float g_deg[NNODES];
__device__ float g_dinv[NNODES];
__device__ float g_sum[HID];
__device__ float g_sumsq[HID];

// ---------------- SGEMM: C[M,256] = A[M,K] @ B[K,256] ----------------
// 128x128 block tile, BK=8, 256 threads, 8x8 microtile, float4 ld/st.
#define GBM 128
#define GBN 128
#define GBK 8
#define GTM 8
#define GTN 8

__global__ __launch_bounds__(256) void sgemm_kernel(
    int M, int K, const float* __restrict__ A, const float* __restrict__ B,
    float* __restrict__ C) {
  const int cRow = blockIdx.y;
  const int cCol = blockIdx.x;

  __shared__ float As[GBK * GBM];   // transposed: As[k*GBM + m]
  __shared__ float Bs[GBK * GBN];

  const int tid = threadIdx.x;
  const int threadRow = tid >> 4;          // 0..15
  const int threadCol = tid & 15;          // 0..15
  const int innerRowA = tid >> 1;          // 0..127
  const int innerColA = (tid & 1) * 4;     // 0 or 4
  const int innerRowB = tid >> 5;          // 0..7
  const int innerColB = (tid & 31) * 4;    // 0..124

  const float* Ab = A + (size_t)cRow * GBM * K;
  const float* Bb = B + cCol * GBN;

  float acc[GTM * GTN];
#pragma unroll
  for (int i = 0; i < GTM * GTN; i++) acc[i] = 0.f;
  float regM[GTM], regN[GTN];

  const int gRowA = cRow * GBM + innerRowA;

  for (int bk = 0; bk < K; bk += GBK) {
    float4 a4 = make_float4(0.f, 0.f, 0.f, 0.f);
    if (gRowA < M)
      a4 = *reinterpret_cast<const float4*>(Ab + (size_t)innerRowA * K + bk + innerColA);
    As[(innerColA + 0) * GBM + innerRowA] = a4.x;
    As[(innerColA + 1) * GBM + innerRowA] = a4.y;
    As[(innerColA + 2) * GBM + innerRowA] = a4.z;
    As[(innerColA + 3) * GBM + innerRowA] = a4.w;
    *reinterpret_cast<float4*>(&Bs[innerRowB * GBN + innerColB]) =
        *reinterpret_cast<const float4*>(Bb + (size_t)(bk + innerRowB) * HID + innerColB);
    __syncthreads();

#pragma unroll
    for (int k = 0; k < GBK; k++) {
#pragma unroll
      for (int i = 0; i < GTM; i++) regM[i] = As[k * GBM + threadRow * GTM + i];
#pragma unroll
      for (int j = 0; j < GTN; j++) regN[j] = Bs[k * GBN + threadCol * GTN + j];
#pragma unroll
      for (int i = 0; i < GTM; i++)
#pragma unroll
        for (int j = 0; j < GTN; j++) acc[i * GTN + j] += regM[i] * regN[j];
    }
    __syncthreads();
  }

#pragma unroll
  for (int i = 0; i < GTM; i++) {
    int r = cRow * GBM + threadRow * GTM + i;
    if (r < M) {
#pragma unroll
      for (int j = 0; j < GTN; j += 4) {
        float4 v = make_float4(acc[i * GTN + j], acc[i * GTN + j + 1],
                               acc[i * GTN + j + 2], acc[i * GTN + j + 3]);
        *reinterpret_cast<float4*>(C + (size_t)r * HID + cCol * GBN +
                                   threadCol * GTN + j) = v;
      }
    }
  }
}

// ---------------- degree kernels ----------------
__global__ void deg_init_kernel(float* deg, int n) {
  int i = blockIdx.x * blockDim.x + threadIdx.x;
  if (i < n) deg[i] = 1.0f;  // self loop
}

__global__ void deg_count_kernel(const int* __restrict__ dst, float* deg, int e) {
  int i = blockIdx.x * blockDim.x + threadIdx.x;
  if (i < e) atomicAdd(&deg[dst[i]], 1.0f);
}

__global__ void deg_fin_kernel(const float* __restrict__ deg, float* dinv, int n) {
  int i = blockIdx.x * blockDim.x + threadIdx.x;
  if (i < n) dinv[i] = rsqrtf(deg[i]);
}

// ---------------- aggregation ----------------
// agg = h * (1/deg) + bias  (self-loop term + bias init; writes every element)
__global__ void init_agg_kernel(const float* __restrict__ h,
                                const float* __restrict__ deg,
                                const float* __restrict__ bias,
                                float* __restrict__ agg, int n) {
  size_t idx = (size_t)blockIdx.x * blockDim.x + threadIdx.x;
  if (idx < (size_t)n * HID) {
    int i = (int)(idx >> 8);   // HID == 256
    int f = (int)(idx & 255);
    agg[idx] = h[idx] * (1.0f / deg[i]) + bias[f];
  }
}

// one block (256 threads) per edge: agg[dst] += h[src] * dinv[src]*dinv[dst]
__global__ __launch_bounds__(HID) void edge_scatter_kernel(
    const int* __restrict__ src, const int* __restrict__ dst,
    const float* __restrict__ h, const float* __restrict__ dinv,
    float* __restrict__ agg, int e) {
  int ei = blockIdx.x;
  if (ei >= e) return;
  int s = __ldg(&src[ei]);
  int d = __ldg(&dst[ei]);
  float c = __ldg(&dinv[s]) * __ldg(&dinv[d]);
  int f = threadIdx.x;
  float v = __ldg(&h[(size_t)s * HID + f]) * c;
  atomicAdd(&agg[(size_t)d * HID + f], v);
}

// ---------------- batchnorm + relu ----------------
__global__ void bn_zero_kernel(float* s, float* sq) {
  int t = threadIdx.x;
  if (t < HID) { s[t] = 0.f; sq[t] = 0.f; }
}

#define BN_RPB 256
__global__ __launch_bounds__(HID) void bn_partial_kernel(
    const float* __restrict__ h, float* s, float* sq, int n) {
  int col = threadIdx.x;
  int r0 = blockIdx.x * BN_RPB;
  int r1 = min(r0 + BN_RPB, n);
  float ps = 0.f, psq = 0.f;
  for (int r = r0; r < r1; r++) {
    float v = h[(size_t)r * HID + col];
    ps += v;
    psq += v * v;
  }
  atomicAdd(&s[col], ps);
  atomicAdd(&sq[col], psq);
}

__global__ void bn_apply_relu_kernel(const float* __restrict__ h,
                                     const float* __restrict__ s,
                                     const float* __restrict__ sq,
                                     const float* __restrict__ gamma,
                                     const float* __restrict__ beta,
                                     float* __restrict__ out, int n) {
  size_t idx = (size_t)blockIdx.x * blockDim.x + threadIdx.x;
  if (idx < (size_t)n * HID) {
    int f = (int)(idx & 255);
    const float invN = 1.0f / (float)NNODES;
    float mu = __ldg(&s[f]) * invN;
    float var = __ldg(&sq[f]) * invN - mu * mu;
    float scale = __ldg(&gamma[f]) * rsqrtf(var + BN_EPS);
    float v = (h[idx] - mu) * scale + __ldg(&beta[f]);
    out[idx] = fmaxf(v, 0.0f);
  }
}

// ---------------- launch ----------------
extern "C" void kernel_launch(void* const* d_in, const int* in_sizes, int n_in,
                              void* d_out, int out_size) {
  const float* x   = (const float*)d_in[0];
  const int*   ei  = (const int*)d_in[1];
  const float* W1  = (const float*)d_in[2];
  const float* b1  = (const float*)d_in[3];
  const float* g1  = (const float*)d_in[4];
  const float* be1 = (const float*)d_in[5];
  const float* W2  = (const float*)d_in[6];
  const float* b2  = (const float*)d_in[7];
  const float* g2  = (const float*)d_in[8];
  const float* be2 = (const float*)d_in[9];

  const int M = NNODES;
  const int E = in_sizes[1] / 2;
  const int* src = ei;
  const int* dst = ei + E;
  float* out = (float*)d_out;

  float *bufA, *bufB, *deg, *dinv, *bsum, *bsumsq;
  cudaGetSymbolAddress((void**)&bufA, g_bufA);
  cudaGetSymbolAddress((void**)&bufB, g_bufB);
  cudaGetSymbolAddress((void**)&deg, g_deg);
  cudaGetSymbolAddress((void**)&dinv, g_dinv);
  cudaGetSymbolAddress((void**)&bsum, g_sum);
  cudaGetSymbolAddress((void**)&bsumsq, g_sumsq);

  const int elemGrid = (int)(((size_t)M * HID + 255) / 256);
  const dim3 gemmGrid(HID / GBN, (M + GBM - 1) / GBM);
  const int bnGrid = (M + BN_RPB - 1) / BN_RPB;

  // degrees (shared by both layers)
  deg_init_kernel<<<(M + 255) / 256, 256>>>(deg, M);
  deg_count_kernel<<<(E + 255) / 256, 256>>>(dst, deg, E);
  deg_fin_kernel<<<(M + 255) / 256, 256>>>(deg, dinv, M);

  // ---- layer 1 ----
  sgemm_kernel<<<gemmGrid, 256>>>(M, INDIM, x, W1, bufA);                 // h1 = x@W1
  init_agg_kernel<<<elemGrid, 256>>>(bufA, deg, b1, bufB, M);             // self + bias
  edge_scatter_kernel<<<E, HID>>>(src, dst, bufA, dinv, bufB, E);         // scatter-add
  bn_zero_kernel<<<1, HID>>>(bsum, bsumsq);
  bn_partial_kernel<<<bnGrid, HID>>>(bufB, bsum, bsumsq, M);
  bn_apply_relu_kernel<<<elemGrid, 256>>>(bufB, bsum, bsumsq, g1, be1, bufA, M);

  // ---- layer 2 ----
  sgemm_kernel<<<gemmGrid, 256>>>(M, HID, bufA, W2, bufB);                // h2 = h@W2
  init_agg_kernel<<<elemGrid, 256>>>(bufB, deg, b2, out, M);
  edge_scatter_kernel<<<E, HID>>>(src, dst, bufB, dinv, out, E);
  bn_zero_kernel<<<1, HID>>>(bsum, bsumsq);
  bn_partial_kernel<<<bnGrid, HID>>>(out, bsum, bsumsq, M);
  bn_apply_relu_kernel<<<elemGrid, 256>>>(out, bsum, bsumsq, g2, be2, out, M);
}

// round 4
// speedup vs baseline: 1.6406x; 1.6406x over previous
#include <cuda_runtime.h>
#include <cuda_bf16.h>

#define NNODES 100000
#define INDIM 384
#define HID 256
#define BN_EPS 1e-5f

// ---------------- scratch (allocation-free: device globals) ----------------
__device__ __align__(16) float g_bufA[(size_t)NNODES * HID];   // 102.4 MB
__device__ __align__(16) float g_bufB[(size_t)NNODES * HID];   // 102.4 MB
__device__ __align__(16) float g_bufC[(size_t)NNODES * HID];   // 102.4 MB (agg scratch)
__device__ float g_deg[NNODES];
__device__ float g_dinv[NNODES];
__device__ float g_sum[HID];
__device__ float g_sumsq[HID];

// ---------------- SGEMM with fused agg-init epilogue ----------------
// C[M,256] = A[M,K] @ B[K,256];  Cagg = C * (1/deg[row]) + bias[col]
#define GBM 128
#define GBN 128
#define GBK 8
#define GTM 8
#define GTN 8

__global__ __launch_bounds__(256) void sgemm_fused_kernel(
    int M, int K, const float* __restrict__ A, const float* __restrict__ B,
    const float* __restrict__ deg, const float* __restrict__ bias,
    float* __restrict__ C, float* __restrict__ Cagg) {
  const int cRow = blockIdx.y;
  const int cCol = blockIdx.x;

  __shared__ float As[GBK * GBM];   // transposed: As[k*GBM + m]
  __shared__ float Bs[GBK * GBN];

  const int tid = threadIdx.x;
  const int threadRow = tid >> 4;          // 0..15
  const int threadCol = tid & 15;          // 0..15
  const int innerRowA = tid >> 1;          // 0..127
  const int innerColA = (tid & 1) * 4;     // 0 or 4
  const int innerRowB = tid >> 5;          // 0..7
  const int innerColB = (tid & 31) * 4;    // 0..124

  const float* Ab = A + (size_t)cRow * GBM * K;
  const float* Bb = B + cCol * GBN;

  float acc[GTM * GTN];
#pragma unroll
  for (int i = 0; i < GTM * GTN; i++) acc[i] = 0.f;
  float regM[GTM], regN[GTN];

  const int gRowA = cRow * GBM + innerRowA;

  for (int bk = 0; bk < K; bk += GBK) {
    float4 a4 = make_float4(0.f, 0.f, 0.f, 0.f);
    if (gRowA < M)
      a4 = *reinterpret_cast<const float4*>(Ab + (size_t)innerRowA * K + bk + innerColA);
    As[(innerColA + 0) * GBM + innerRowA] = a4.x;
    As[(innerColA + 1) * GBM + innerRowA] = a4.y;
    As[(innerColA + 2) * GBM + innerRowA] = a4.z;
    As[(innerColA + 3) * GBM + innerRowA] = a4.w;
    *reinterpret_cast<float4*>(&Bs[innerRowB * GBN + innerColB]) =
        *reinterpret_cast<const float4*>(Bb + (size_t)(bk + innerRowB) * HID + innerColB);
    __syncthreads();

#pragma unroll
    for (int k = 0; k < GBK; k++) {
#pragma unroll
      for (int i = 0; i < GTM; i++) regM[i] = As[k * GBM + threadRow * GTM + i];
#pragma unroll
      for (int j = 0; j < GTN; j++) regN[j] = Bs[k * GBN + threadCol * GTN + j];
#pragma unroll
      for (int i = 0; i < GTM; i++)
#pragma unroll
        for (int j = 0; j < GTN; j++) acc[i * GTN + j] += regM[i] * regN[j];
    }
    __syncthreads();
  }

  // bias for this thread's 8 columns
  float bcol[GTN];
#pragma unroll
  for (int j = 0; j < GTN; j++)
    bcol[j] = __ldg(&bias[cCol * GBN + threadCol * GTN + j]);

#pragma unroll
  for (int i = 0; i < GTM; i++) {
    int r = cRow * GBM + threadRow * GTM + i;
    if (r < M) {
      float invdeg = 1.0f / __ldg(&deg[r]);
      size_t base = (size_t)r * HID + cCol * GBN + threadCol * GTN;
#pragma unroll
      for (int j = 0; j < GTN; j += 4) {
        float4 v = make_float4(acc[i * GTN + j], acc[i * GTN + j + 1],
                               acc[i * GTN + j + 2], acc[i * GTN + j + 3]);
        *reinterpret_cast<float4*>(C + base + j) = v;
        float4 va = make_float4(v.x * invdeg + bcol[j], v.y * invdeg + bcol[j + 1],
                                v.z * invdeg + bcol[j + 2], v.w * invdeg + bcol[j + 3]);
        *reinterpret_cast<float4*>(Cagg + base + j) = va;
      }
    }
  }
}

// ---------------- degree kernels ----------------
__global__ void deg_init_kernel(float* deg, int n) {
  int i = blockIdx.x * blockDim.x + threadIdx.x;
  if (i < n) deg[i] = 1.0f;  // self loop
}

__global__ void deg_count_kernel(const int* __restrict__ dst, float* deg, int e) {
  int i = blockIdx.x * blockDim.x + threadIdx.x;
  if (i < e) atomicAdd(&deg[dst[i]], 1.0f);
}

__global__ void deg_fin_kernel(const float* __restrict__ deg, float* dinv, int n) {
  int i = blockIdx.x * blockDim.x + threadIdx.x;
  if (i < n) dinv[i] = rsqrtf(deg[i]);
}

// ---------------- aggregation: warp per edge, float4 gather + v4 RED ----------------
__global__ __launch_bounds__(256) void edge_scatter_v4_kernel(
    const int* __restrict__ src, const int* __restrict__ dst,
    const float* __restrict__ h, const float* __restrict__ dinv,
    float* __restrict__ agg, int e) {
  int ei = blockIdx.x * 8 + (threadIdx.x >> 5);
  if (ei >= e) return;
  int lane = threadIdx.x & 31;
  int s = __ldg(&src[ei]);
  int d = __ldg(&dst[ei]);
  float c = __ldg(&dinv[s]) * __ldg(&dinv[d]);
  const float4* hs =
      reinterpret_cast<const float4*>(h + (size_t)s * HID) + lane * 2;
  float4 a = __ldg(hs);
  float4 b = __ldg(hs + 1);
  float* base = agg + (size_t)d * HID + lane * 8;
  asm volatile("red.global.add.v4.f32 [%0], {%1,%2,%3,%4};" ::"l"(base),
               "f"(a.x * c), "f"(a.y * c), "f"(a.z * c), "f"(a.w * c)
               : "memory");
  asm volatile("red.global.add.v4.f32 [%0], {%1,%2,%3,%4};" ::"l"(base + 4),
               "f"(b.x * c), "f"(b.y * c), "f"(b.z * c), "f"(b.w * c)
               : "memory");
}

// ---------------- batchnorm + relu ----------------
__global__ void bn_zero_kernel(float* s, float* sq) {
  int t = threadIdx.x;
  if (t < HID) { s[t] = 0.f; sq[t] = 0.f; }
}

#define BN_RPB 256
__global__ __launch_bounds__(HID) void bn_partial_kernel(
    const float* __restrict__ h, float* s, float* sq, int n) {
  int col = threadIdx.x;
  int r0 = blockIdx.x * BN_RPB;
  int r1 = min(r0 + BN_RPB, n);
  float ps = 0.f, psq = 0.f;
  for (int r = r0; r < r1; r++) {
    float v = h[(size_t)r * HID + col];
    ps += v;
    psq += v * v;
  }
  atomicAdd(&s[col], ps);
  atomicAdd(&sq[col], psq);
}

// float4-vectorized BN apply + ReLU
__global__ __launch_bounds__(256) void bn_apply_relu_kernel(
    const float* __restrict__ h, const float* __restrict__ s,
    const float* __restrict__ sq, const float* __restrict__ gamma,
    const float* __restrict__ beta, float* __restrict__ out, int n) {
  size_t idx = (size_t)blockIdx.x * blockDim.x + threadIdx.x;  // float4 index
  size_t total = (size_t)n * (HID / 4);
  if (idx >= total) return;
  int f4 = (int)(idx & 63);  // HID/4 == 64
  int f = f4 * 4;
  const float invN = 1.0f / (float)NNODES;
  float4 mu, sc, bt;
  {
    float4 ss = *reinterpret_cast<const float4*>(s + f);
    float4 qq = *reinterpret_cast<const float4*>(sq + f);
    float4 gg = *reinterpret_cast<const float4*>(gamma + f);
    bt = *reinterpret_cast<const float4*>(beta + f);
    mu = make_float4(ss.x * invN, ss.y * invN, ss.z * invN, ss.w * invN);
    sc.x = gg.x * rsqrtf(qq.x * invN - mu.x * mu.x + BN_EPS);
    sc.y = gg.y * rsqrtf(qq.y * invN - mu.y * mu.y + BN_EPS);
    sc.z = gg.z * rsqrtf(qq.z * invN - mu.z * mu.z + BN_EPS);
    sc.w = gg.w * rsqrtf(qq.w * invN - mu.w * mu.w + BN_EPS);
  }
  float4 v = reinterpret_cast<const float4*>(h)[idx];
  float4 o;
  o.x = fmaxf((v.x - mu.x) * sc.x + bt.x, 0.f);
  o.y = fmaxf((v.y - mu.y) * sc.y + bt.y, 0.f);
  o.z = fmaxf((v.z - mu.z) * sc.z + bt.z, 0.f);
  o.w = fmaxf((v.w - mu.w) * sc.w + bt.w, 0.f);
  reinterpret_cast<float4*>(out)[idx] = o;
}

// ---------------- launch ----------------
extern "C" void kernel_launch(void* const* d_in, const int* in_sizes, int n_in,
                              void* d_out, int out_size) {
  const float* x   = (const float*)d_in[0];
  const int*   ei  = (const int*)d_in[1];
  const float* W1  = (const float*)d_in[2];
  const float* b1  = (const float*)d_in[3];
  const float* g1  = (const float*)d_in[4];
  const float* be1 = (const float*)d_in[5];
  const float* W2  = (const float*)d_in[6];
  const float* b2  = (const float*)d_in[7];
  const float* g2  = (const float*)d_in[8];
  const float* be2 = (const float*)d_in[9];

  const int M = NNODES;
  const int E = in_sizes[1] / 2;
  const int* src = ei;
  const int* dst = ei + E;
  float* out = (float*)d_out;

  float *bufA, *bufB, *bufC, *deg, *dinv, *bsum, *bsumsq;
  cudaGetSymbolAddress((void**)&bufA, g_bufA);
  cudaGetSymbolAddress((void**)&bufB, g_bufB);
  cudaGetSymbolAddress((void**)&bufC, g_bufC);
  cudaGetSymbolAddress((void**)&deg, g_deg);
  cudaGetSymbolAddress((void**)&dinv, g_dinv);
  cudaGetSymbolAddress((void**)&bsum, g_sum);
  cudaGetSymbolAddress((void**)&bsumsq, g_sumsq);

  const int vecGrid = (int)(((size_t)M * (HID / 4) + 255) / 256);
  const dim3 gemmGrid(HID / GBN, (M + GBM - 1) / GBM);
  const int bnGrid = (M + BN_RPB - 1) / BN_RPB;
  const int scatGrid = (E + 7) / 8;

  // degrees (shared by both layers)
  deg_init_kernel<<<(M + 255) / 256, 256>>>(deg, M);
  deg_count_kernel<<<(E + 255) / 256, 256>>>(dst, deg, E);
  deg_fin_kernel<<<(M + 255) / 256, 256>>>(deg, dinv, M);

  // ---- layer 1 ----
  // h1 = x@W1 -> bufA ; agg-init = h1/deg + b1 -> bufB
  sgemm_fused_kernel<<<gemmGrid, 256>>>(M, INDIM, x, W1, deg, b1, bufA, bufB);
  edge_scatter_v4_kernel<<<scatGrid, 256>>>(src, dst, bufA, dinv, bufB, E);
  bn_zero_kernel<<<1, HID>>>(bsum, bsumsq);
  bn_partial_kernel<<<bnGrid, HID>>>(bufB, bsum, bsumsq, M);
  bn_apply_relu_kernel<<<vecGrid, 256>>>(bufB, bsum, bsumsq, g1, be1, bufA, M);

  // ---- layer 2 ----
  // h2 = h@W2 -> bufC ; agg-init -> out
  sgemm_fused_kernel<<<gemmGrid, 256>>>(M, HID, bufA, W2, deg, b2, bufC, out);
  edge_scatter_v4_kernel<<<scatGrid, 256>>>(src, dst, bufC, dinv, out, E);
  bn_zero_kernel<<<1, HID>>>(bsum, bsumsq);
  bn_partial_kernel<<<bnGrid, HID>>>(out, bsum, bsumsq, M);
  bn_apply_relu_kernel<<<vecGrid, 256>>>(out, bsum, bsumsq, g2, be2, out, M);
}

// round 12
// speedup vs baseline: 2.2938x; 1.3982x over previous
#include <cuda_runtime.h>
#include <cuda_bf16.h>
#include <cstdint>

#define NNODES 100000
#define INDIM 384
#define HID 256
#define BN_EPS 1e-5f

// ---------------- scratch (allocation-free: device globals) ----------------
__device__ __align__(16) float g_bufA[(size_t)NNODES * HID];   // 102.4 MB
__device__ __align__(16) float g_bufB[(size_t)NNODES * HID];   // 102.4 MB
__device__ __align__(16) float g_bufC[(size_t)NNODES * HID];   // 102.4 MB
__device__ float g_deg[NNODES];
__device__ float g_dinv[NNODES];
__device__ float g_sum[HID];
__device__ float g_sumsq[HID];
// split-bf16 weights, [N, K] layout (row n holds K values of W[:,n])
__device__ __align__(16) __nv_bfloat16 g_w1hi[HID * INDIM];
__device__ __align__(16) __nv_bfloat16 g_w1lo[HID * INDIM];
__device__ __align__(16) __nv_bfloat16 g_w2hi[HID * HID];
__device__ __align__(16) __nv_bfloat16 g_w2lo[HID * HID];

// ---------------- helpers ----------------
__device__ __forceinline__ uint32_t smem_u32(const void* p) {
  uint32_t a;
  asm("{ .reg .u64 t; cvta.to.shared.u64 t, %1; cvt.u32.u64 %0, t; }"
      : "=r"(a) : "l"(p));
  return a;
}
__device__ __forceinline__ void split2(float a, float b, uint32_t& hi,
                                       uint32_t& lo) {
  __nv_bfloat162 h = __floats2bfloat162_rn(a, b);
  float ra = a - __bfloat162float(h.x);
  float rb = b - __bfloat162float(h.y);
  __nv_bfloat162 l = __floats2bfloat162_rn(ra, rb);
  hi = *reinterpret_cast<uint32_t*>(&h);
  lo = *reinterpret_cast<uint32_t*>(&l);
}

#define LDMX4(r, a)                                                        \
  asm volatile("ldmatrix.sync.aligned.m8n8.x4.shared.b16 {%0,%1,%2,%3}, [%4];" \
               : "=r"((r)[0]), "=r"((r)[1]), "=r"((r)[2]), "=r"((r)[3])    \
               : "r"(a))

#define MMA16816(d, a, b)                                                    \
  asm volatile(                                                              \
      "mma.sync.aligned.m16n8k16.row.col.f32.bf16.bf16.f32 "                 \
      "{%0,%1,%2,%3},{%4,%5,%6,%7},{%8,%9},{%0,%1,%2,%3};"                   \
      : "+f"((d)[0]), "+f"((d)[1]), "+f"((d)[2]), "+f"((d)[3])               \
      : "r"((a)[0]), "r"((a)[1]), "r"((a)[2]), "r"((a)[3]), "r"((b)[0]),     \
        "r"((b)[1]))

// ---------------- mma.sync split-bf16 GEMM ----------------
// C[M,256] = A[M,K] @ W[K,256] (W given as [N,K] bf16 hi/lo)
// Cagg = C/deg[row] + bias[col].  CTA: 128 rows x 256 cols, BK=32, 512 thr.
#define SSTR 40            // smem row stride in halves (padding vs conflicts)
#define SA_HI 0            // 128*40 halves
#define SA_LO 5120
#define SB_HI 10240        // 256*40 halves
#define SB_LO 20480
#define GEMM_SMEM (30720 * 2)

__global__ void __launch_bounds__(512, 1)
gemm_mma_kernel(int M, int K, const float* __restrict__ A,
                const __nv_bfloat16* __restrict__ Whi,
                const __nv_bfloat16* __restrict__ Wlo,
                const float* __restrict__ deg, const float* __restrict__ bias,
                float* __restrict__ C, float* __restrict__ Cagg) {
  extern __shared__ char smem[];
  const uint32_t sb = smem_u32(smem);
  const int tid = threadIdx.x;
  const int lane = tid & 31;
  const int wid = tid >> 5;
  const int wm = wid & 3;       // warp row 0..3 (32 rows each)
  const int wn = wid >> 2;      // warp col 0..3 (64 cols each)
  const int rbase = blockIdx.x * 128;
  const int NC = K >> 5;

  float acc[2][8][4];
#pragma unroll
  for (int i = 0; i < 2; i++)
#pragma unroll
    for (int j = 0; j < 8; j++)
#pragma unroll
      for (int q = 0; q < 4; q++) acc[i][j][q] = 0.f;

  for (int ck = 0; ck < NC; ck++) {
    const int k0 = ck << 5;
    __syncthreads();
    // ---- stage A: 128 rows x 32 f32 -> bf16 hi/lo (1024 float4 units) ----
#pragma unroll
    for (int it = 0; it < 2; it++) {
      int u = tid + it * 512;
      int row = u >> 3;
      int cg = (u & 7) * 4;
      int gr = rbase + row;
      float4 v = make_float4(0.f, 0.f, 0.f, 0.f);
      if (gr < M)
        v = *reinterpret_cast<const float4*>(A + (size_t)gr * K + k0 + cg);
      uint2 uh, ul;
      split2(v.x, v.y, uh.x, ul.x);
      split2(v.z, v.w, uh.y, ul.y);
      uint32_t idx = (uint32_t)row * SSTR + cg;
      *reinterpret_cast<uint2*>(smem + (size_t)(SA_HI + idx) * 2) = uh;
      *reinterpret_cast<uint2*>(smem + (size_t)(SA_LO + idx) * 2) = ul;
    }
    // ---- stage B: 256 rows x 32 halves hi/lo (1024 uint4-of-8-halves) ----
#pragma unroll
    for (int it = 0; it < 2; it++) {
      int u = tid + it * 512;
      int row = u >> 2;
      int cg = (u & 3) * 8;
      size_t goff = (size_t)row * K + k0 + cg;
      uint4 vh = *reinterpret_cast<const uint4*>(Whi + goff);
      uint4 vl = *reinterpret_cast<const uint4*>(Wlo + goff);
      uint32_t idx = (uint32_t)row * SSTR + cg;
      *reinterpret_cast<uint4*>(smem + (size_t)(SB_HI + idx) * 2) = vh;
      *reinterpret_cast<uint4*>(smem + (size_t)(SB_LO + idx) * 2) = vl;
    }
    __syncthreads();

    // ---- compute: 2 k16 steps ----
#pragma unroll
    for (int kk = 0; kk < 32; kk += 16) {
      uint32_t ahi[2][4], alo[2][4];
#pragma unroll
      for (int mf = 0; mf < 2; mf++) {
        int ar = wm * 32 + mf * 16 + (lane & 15);
        int ac = kk + ((lane >> 4) << 3);
        uint32_t ad = sb + (uint32_t)(SA_HI + ar * SSTR + ac) * 2;
        LDMX4(ahi[mf], ad);
        LDMX4(alo[mf], ad + (SA_LO - SA_HI) * 2);
      }
#pragma unroll
      for (int ng = 0; ng < 4; ng++) {
        int nb = wn * 64 + ng * 16;
        int br = nb + ((lane >> 4) & 1) * 8 + (lane & 7);
        int bc = kk + ((lane >> 3) & 1) * 8;
        uint32_t bd = sb + (uint32_t)(SB_HI + br * SSTR + bc) * 2;
        uint32_t bhi[4], blo[4];
        LDMX4(bhi, bd);
        LDMX4(blo, bd + (SB_LO - SB_HI) * 2);
#pragma unroll
        for (int mf = 0; mf < 2; mf++) {
#pragma unroll
          for (int nf = 0; nf < 2; nf++) {
            float* d = acc[mf][ng * 2 + nf];
            MMA16816(d, ahi[mf], bhi + nf * 2);
            MMA16816(d, ahi[mf], blo + nf * 2);
            MMA16816(d, alo[mf], bhi + nf * 2);
          }
        }
      }
    }
  }

  // ---- epilogue: C and Cagg = C/deg + bias ----
#pragma unroll
  for (int mf = 0; mf < 2; mf++) {
    int r0 = rbase + wm * 32 + mf * 16 + (lane >> 2);
    int r1 = r0 + 8;
    float id0 = (r0 < M) ? (1.0f / __ldg(&deg[r0])) : 0.f;
    float id1 = (r1 < M) ? (1.0f / __ldg(&deg[r1])) : 0.f;
#pragma unroll
    for (int ng = 0; ng < 4; ng++) {
#pragma unroll
      for (int nf = 0; nf < 2; nf++) {
        float* d = acc[mf][ng * 2 + nf];
        int col = wn * 64 + ng * 16 + nf * 8 + (lane & 3) * 2;
        float b0 = __ldg(&bias[col]);
        float b1 = __ldg(&bias[col + 1]);
        if (r0 < M) {
          size_t o = (size_t)r0 * HID + col;
          *reinterpret_cast<float2*>(C + o) = make_float2(d[0], d[1]);
          *reinterpret_cast<float2*>(Cagg + o) =
              make_float2(d[0] * id0 + b0, d[1] * id0 + b1);
        }
        if (r1 < M) {
          size_t o = (size_t)r1 * HID + col;
          *reinterpret_cast<float2*>(C + o) = make_float2(d[2], d[3]);
          *reinterpret_cast<float2*>(Cagg + o) =
              make_float2(d[2] * id1 + b0, d[3] * id1 + b1);
        }
      }
    }
  }
}

// ---------------- weight split prep ----------------
__global__ void wsplit_kernel(const float* __restrict__ W,
                              __nv_bfloat16* __restrict__ hi,
                              __nv_bfloat16* __restrict__ lo, int K, int N) {
  int idx = blockIdx.x * blockDim.x + threadIdx.x;
  if (idx < K * N) {
    int k = idx / N, n = idx % N;
    float v = W[idx];
    __nv_bfloat16 h = __float2bfloat16(v);
    hi[n * K + k] = h;
    lo[n * K + k] = __float2bfloat16(v - __bfloat162float(h));
  }
}

// ---------------- degree kernels ----------------
__global__ void deg_init_kernel(float* deg, int n) {
  int i = blockIdx.x * blockDim.x + threadIdx.x;
  if (i < n) deg[i] = 1.0f;
}
__global__ void deg_count_kernel(const int* __restrict__ dst, float* deg, int e) {
  int i = blockIdx.x * blockDim.x + threadIdx.x;
  if (i < e) atomicAdd(&deg[dst[i]], 1.0f);
}
__global__ void deg_fin_kernel(const float* __restrict__ deg, float* dinv, int n) {
  int i = blockIdx.x * blockDim.x + threadIdx.x;
  if (i < n) dinv[i] = rsqrtf(deg[i]);
}

// ---------------- aggregation: warp per edge, float4 gather + v4 RED ----------------
__global__ __launch_bounds__(256) void edge_scatter_v4_kernel(
    const int* __restrict__ src, const int* __restrict__ dst,
    const float* __restrict__ h, const float* __restrict__ dinv,
    float* __restrict__ agg, int e) {
  int ei = blockIdx.x * 8 + (threadIdx.x >> 5);
  if (ei >= e) return;
  int lane = threadIdx.x & 31;
  int s = __ldg(&src[ei]);
  int d = __ldg(&dst[ei]);
  float c = __ldg(&dinv[s]) * __ldg(&dinv[d]);
  const float4* hs = reinterpret_cast<const float4*>(h + (size_t)s * HID) + lane * 2;
  float4 a = __ldg(hs);
  float4 b = __ldg(hs + 1);
  float* base = agg + (size_t)d * HID + lane * 8;
  asm volatile("red.global.add.v4.f32 [%0], {%1,%2,%3,%4};" ::"l"(base),
               "f"(a.x * c), "f"(a.y * c), "f"(a.z * c), "f"(a.w * c) : "memory");
  asm volatile("red.global.add.v4.f32 [%0], {%1,%2,%3,%4};" ::"l"(base + 4),
               "f"(b.x * c), "f"(b.y * c), "f"(b.z * c), "f"(b.w * c) : "memory");
}

// ---------------- batchnorm + relu ----------------
__global__ void bn_zero_kernel(float* s, float* sq) {
  int t = threadIdx.x;
  if (t < HID) { s[t] = 0.f; sq[t] = 0.f; }
}

#define BN_RPB 256
__global__ __launch_bounds__(HID) void bn_partial_kernel(
    const float* __restrict__ h, float* s, float* sq, int n) {
  int col = threadIdx.x;
  int r0 = blockIdx.x * BN_RPB;
  int r1 = min(r0 + BN_RPB, n);
  float ps = 0.f, psq = 0.f;
  for (int r = r0; r < r1; r++) {
    float v = h[(size_t)r * HID + col];
    ps += v;
    psq += v * v;
  }
  atomicAdd(&s[col], ps);
  atomicAdd(&sq[col], psq);
}

__global__ __launch_bounds__(256) void bn_apply_relu_kernel(
    const float* __restrict__ h, const float* __restrict__ s,
    const float* __restrict__ sq, const float* __restrict__ gamma,
    const float* __restrict__ beta, float* __restrict__ out, int n) {
  size_t idx = (size_t)blockIdx.x * blockDim.x + threadIdx.x;  // float4 index
  size_t total = (size_t)n * (HID / 4);
  if (idx >= total) return;
  int f = (int)(idx & 63) * 4;
  const float invN = 1.0f / (float)NNODES;
  float4 mu, sc, bt;
  {
    float4 ss = *reinterpret_cast<const float4*>(s + f);
    float4 qq = *reinterpret_cast<const float4*>(sq + f);
    float4 gg = *reinterpret_cast<const float4*>(gamma + f);
    bt = *reinterpret_cast<const float4*>(beta + f);
    mu = make_float4(ss.x * invN, ss.y * invN, ss.z * invN, ss.w * invN);
    sc.x = gg.x * rsqrtf(qq.x * invN - mu.x * mu.x + BN_EPS);
    sc.y = gg.y * rsqrtf(qq.y * invN - mu.y * mu.y + BN_EPS);
    sc.z = gg.z * rsqrtf(qq.z * invN - mu.z * mu.z + BN_EPS);
    sc.w = gg.w * rsqrtf(qq.w * invN - mu.w * mu.w + BN_EPS);
  }
  float4 v = reinterpret_cast<const float4*>(h)[idx];
  float4 o;
  o.x = fmaxf((v.x - mu.x) * sc.x + bt.x, 0.f);
  o.y = fmaxf((v.y - mu.y) * sc.y + bt.y, 0.f);
  o.z = fmaxf((v.z - mu.z) * sc.z + bt.z, 0.f);
  o.w = fmaxf((v.w - mu.w) * sc.w + bt.w, 0.f);
  reinterpret_cast<float4*>(out)[idx] = o;
}

// ---------------- launch ----------------
extern "C" void kernel_launch(void* const* d_in, const int* in_sizes, int n_in,
                              void* d_out, int out_size) {
  const float* x   = (const float*)d_in[0];
  const int*   ei  = (const int*)d_in[1];
  const float* W1  = (const float*)d_in[2];
  const float* b1  = (const float*)d_in[3];
  const float* g1  = (const float*)d_in[4];
  const float* be1 = (const float*)d_in[5];
  const float* W2  = (const float*)d_in[6];
  const float* b2  = (const float*)d_in[7];
  const float* g2  = (const float*)d_in[8];
  const float* be2 = (const float*)d_in[9];

  const int M = NNODES;
  const int E = in_sizes[1] / 2;
  const int* src = ei;
  const int* dst = ei + E;
  float* out = (float*)d_out;

  float *bufA, *bufB, *bufC, *deg, *dinv, *bsum, *bsumsq;
  __nv_bfloat16 *w1hi, *w1lo, *w2hi, *w2lo;
  cudaGetSymbolAddress((void**)&bufA, g_bufA);
  cudaGetSymbolAddress((void**)&bufB, g_bufB);
  cudaGetSymbolAddress((void**)&bufC, g_bufC);
  cudaGetSymbolAddress((void**)&deg, g_deg);
  cudaGetSymbolAddress((void**)&dinv, g_dinv);
  cudaGetSymbolAddress((void**)&bsum, g_sum);
  cudaGetSymbolAddress((void**)&bsumsq, g_sumsq);
  cudaGetSymbolAddress((void**)&w1hi, g_w1hi);
  cudaGetSymbolAddress((void**)&w1lo, g_w1lo);
  cudaGetSymbolAddress((void**)&w2hi, g_w2hi);
  cudaGetSymbolAddress((void**)&w2lo, g_w2lo);

  cudaFuncSetAttribute(gemm_mma_kernel,
                       cudaFuncAttributeMaxDynamicSharedMemorySize, GEMM_SMEM);

  const int vecGrid = (int)(((size_t)M * (HID / 4) + 255) / 256);
  const int gemmGrid = (M + 127) / 128;
  const int bnGrid = (M + BN_RPB - 1) / BN_RPB;
  const int scatGrid = (E + 7) / 8;

  // weight split + degrees (shared by both layers)
  wsplit_kernel<<<(INDIM * HID + 255) / 256, 256>>>(W1, w1hi, w1lo, INDIM, HID);
  wsplit_kernel<<<(HID * HID + 255) / 256, 256>>>(W2, w2hi, w2lo, HID, HID);
  deg_init_kernel<<<(M + 255) / 256, 256>>>(deg, M);
  deg_count_kernel<<<(E + 255) / 256, 256>>>(dst, deg, E);
  deg_fin_kernel<<<(M + 255) / 256, 256>>>(deg, dinv, M);

  // ---- layer 1 ----
  gemm_mma_kernel<<<gemmGrid, 512, GEMM_SMEM>>>(M, INDIM, x, w1hi, w1lo, deg,
                                                b1, bufA, bufB);
  edge_scatter_v4_kernel<<<scatGrid, 256>>>(src, dst, bufA, dinv, bufB, E);
  bn_zero_kernel<<<1, HID>>>(bsum, bsumsq);
  bn_partial_kernel<<<bnGrid, HID>>>(bufB, bsum, bsumsq, M);
  bn_apply_relu_kernel<<<vecGrid, 256>>>(bufB, bsum, bsumsq, g1, be1, bufA, M);

  // ---- layer 2 ----
  gemm_mma_kernel<<<gemmGrid, 512, GEMM_SMEM>>>(M, HID, bufA, w2hi, w2lo, deg,
                                                b2, bufC, out);
  edge_scatter_v4_kernel<<<scatGrid, 256>>>(src, dst, bufC, dinv, out, E);
  bn_zero_kernel<<<1, HID>>>(bsum, bsumsq);
  bn_partial_kernel<<<bnGrid, HID>>>(out, bsum, bsumsq, M);
  bn_apply_relu_kernel<<<vecGrid, 256>>>(out, bsum, bsumsq, g2, be2, out, M);
}

// round 17
// speedup vs baseline: 2.3107x; 1.0074x over previous
#include <cuda_runtime.h>
#include <cuda_bf16.h>
#include <cstdint>

#define NNODES 100000
#define MPAD 100096          // NNODES rounded up to 128
#define INDIM 384
#define HID 256
#define BN_EPS 1e-5f

// ---------------- scratch (allocation-free: device globals) ----------------
__device__ __align__(16) float g_bufA[(size_t)NNODES * HID];   // 102.4 MB
__device__ __align__(16) float g_bufB[(size_t)NNODES * HID];   // 102.4 MB
__device__ __align__(16) float g_bufC[(size_t)NNODES * HID];   // 102.4 MB
__device__ float g_deg[NNODES];
__device__ float g_dinv[NNODES];
__device__ float g_sum[HID];
__device__ float g_sumsq[HID];
// split-bf16 A operand (padded rows), [MPAD, K] row-major
__device__ __align__(16) __nv_bfloat16 g_ahi[(size_t)MPAD * INDIM];  // 76.9 MB
__device__ __align__(16) __nv_bfloat16 g_alo[(size_t)MPAD * INDIM];  // 76.9 MB
// split-bf16 weights, [N, K] layout (row n holds K values of W[:,n])
__device__ __align__(16) __nv_bfloat16 g_w1hi[HID * INDIM];
__device__ __align__(16) __nv_bfloat16 g_w1lo[HID * INDIM];
__device__ __align__(16) __nv_bfloat16 g_w2hi[HID * HID];
__device__ __align__(16) __nv_bfloat16 g_w2lo[HID * HID];

// ---------------- helpers ----------------
__device__ __forceinline__ uint32_t smem_u32(const void* p) {
  uint32_t a;
  asm("{ .reg .u64 t; cvta.to.shared.u64 t, %1; cvt.u32.u64 %0, t; }"
      : "=r"(a) : "l"(p));
  return a;
}
__device__ __forceinline__ void split2(float a, float b, uint32_t& hi,
                                       uint32_t& lo) {
  __nv_bfloat162 h = __floats2bfloat162_rn(a, b);
  float ra = a - __bfloat162float(h.x);
  float rb = b - __bfloat162float(h.y);
  __nv_bfloat162 l = __floats2bfloat162_rn(ra, rb);
  hi = *reinterpret_cast<uint32_t*>(&h);
  lo = *reinterpret_cast<uint32_t*>(&l);
}

#define CP16(dst, src)                                                  \
  asm volatile("cp.async.ca.shared.global [%0], [%1], 16;" ::"r"(dst),  \
               "l"(src) : "memory")
#define CP_COMMIT() asm volatile("cp.async.commit_group;" ::: "memory")
template <int N>
__device__ __forceinline__ void cp_wait() {
  asm volatile("cp.async.wait_group %0;" ::"n"(N) : "memory");
}

#define LDMX4(r, a)                                                        \
  asm volatile("ldmatrix.sync.aligned.m8n8.x4.shared.b16 {%0,%1,%2,%3}, [%4];" \
               : "=r"((r)[0]), "=r"((r)[1]), "=r"((r)[2]), "=r"((r)[3])    \
               : "r"(a))

#define MMA16816(d, a, b)                                                    \
  asm volatile(                                                              \
      "mma.sync.aligned.m16n8k16.row.col.f32.bf16.bf16.f32 "                 \
      "{%0,%1,%2,%3},{%4,%5,%6,%7},{%8,%9},{%0,%1,%2,%3};"                   \
      : "+f"((d)[0]), "+f"((d)[1]), "+f"((d)[2]), "+f"((d)[3])               \
      : "r"((a)[0]), "r"((a)[1]), "r"((a)[2]), "r"((a)[3]), "r"((b)[0]),     \
        "r"((b)[1]))

// ---------------- cp.async double-buffered split-bf16 GEMM ----------------
// C[M,256] = A[M,K] @ W[K,256]; A given as bf16 hi/lo [MPAD,K] row-major,
// W as [N,K] bf16 hi/lo.  Cagg = C/deg[row] + bias[col].
// CTA: 128 rows x 256 cols, BK=32, 512 threads, 2-stage cp.async pipeline.
#define SSTR 40                       // smem row stride in halves
#define AHI_B 0                       // A hi: 128*40 halves = 10240 B
#define ALO_B 10240
#define BHI_B 20480                   // B hi: 256*40 halves = 20480 B
#define BLO_B 40960
#define STAGE_B 61440
#define GEMM_SMEM (2 * STAGE_B)

__global__ void __launch_bounds__(512, 1)
gemm_mma_kernel(int M, int K, const __nv_bfloat16* __restrict__ Ahi,
                const __nv_bfloat16* __restrict__ Alo,
                const __nv_bfloat16* __restrict__ Whi,
                const __nv_bfloat16* __restrict__ Wlo,
                const float* __restrict__ deg, const float* __restrict__ bias,
                float* __restrict__ C, float* __restrict__ Cagg) {
  extern __shared__ char smem[];
  const uint32_t sb = smem_u32(smem);
  const int tid = threadIdx.x;
  const int lane = tid & 31;
  const int wid = tid >> 5;
  const int wm = wid & 3;       // warp row 0..3 (32 rows each)
  const int wn = wid >> 2;      // warp col 0..3 (64 cols each)
  const int rbase = blockIdx.x * 128;
  const int NC = K >> 5;

  // per-thread staging coordinates
  // A: 128 rows x 32 halves = 512 x 16B units; unit = tid
  const int arow = tid >> 2;            // 0..127
  const int ach = (tid & 3) * 8;        // halves 0,8,16,24
  const uint32_t a_doff = (uint32_t)(arow * SSTR + ach) * 2;
  const size_t a_goff = (size_t)(rbase + arow) * K + ach;  // padded: no guard

  float acc[2][8][4];
#pragma unroll
  for (int i = 0; i < 2; i++)
#pragma unroll
    for (int j = 0; j < 8; j++)
#pragma unroll
      for (int q = 0; q < 4; q++) acc[i][j][q] = 0.f;

  auto stage = [&](int ck) {
    const uint32_t sbase = sb + (ck & 1) * STAGE_B;
    const int k0 = ck << 5;
    CP16(sbase + AHI_B + a_doff, Ahi + a_goff + k0);
    CP16(sbase + ALO_B + a_doff, Alo + a_goff + k0);
    // B: 256 rows x 32 halves = 1024 x 16B units; unit u = tid + it*512
#pragma unroll
    for (int it = 0; it < 2; it++) {
      int u = tid + it * 512;
      int row = u >> 2;                 // 0..255
      int ch = (u & 3) * 8;             // halves 0,8,16,24
      uint32_t doff = (uint32_t)(row * SSTR + ch) * 2;
      size_t goff = (size_t)row * K + k0 + ch;
      CP16(sbase + BHI_B + doff, Whi + goff);
      CP16(sbase + BLO_B + doff, Wlo + goff);
    }
    CP_COMMIT();
  };

  stage(0);
  for (int ck = 0; ck < NC; ck++) {
    if (ck + 1 < NC) {
      stage(ck + 1);
      cp_wait<1>();
    } else {
      cp_wait<0>();
    }
    __syncthreads();

    const uint32_t base = sb + (ck & 1) * STAGE_B;
#pragma unroll
    for (int kk = 0; kk < 32; kk += 16) {
      uint32_t ahi[2][4], alo[2][4];
#pragma unroll
      for (int mf = 0; mf < 2; mf++) {
        int ar = wm * 32 + mf * 16 + (lane & 15);
        int ac = kk + ((lane >> 4) << 3);
        uint32_t ad = base + AHI_B + (uint32_t)(ar * SSTR + ac) * 2;
        LDMX4(ahi[mf], ad);
        LDMX4(alo[mf], ad + (ALO_B - AHI_B));
      }
#pragma unroll
      for (int ng = 0; ng < 4; ng++) {
        int nb = wn * 64 + ng * 16;
        int br = nb + ((lane >> 4) & 1) * 8 + (lane & 7);
        int bc = kk + ((lane >> 3) & 1) * 8;
        uint32_t bd = base + BHI_B + (uint32_t)(br * SSTR + bc) * 2;
        uint32_t bhi[4], blo[4];
        LDMX4(bhi, bd);
        LDMX4(blo, bd + (BLO_B - BHI_B));
#pragma unroll
        for (int mf = 0; mf < 2; mf++) {
#pragma unroll
          for (int nf = 0; nf < 2; nf++) {
            float* d = acc[mf][ng * 2 + nf];
            MMA16816(d, ahi[mf], bhi + nf * 2);
            MMA16816(d, ahi[mf], blo + nf * 2);
            MMA16816(d, alo[mf], bhi + nf * 2);
          }
        }
      }
    }
    __syncthreads();
  }

  // ---- epilogue: C and Cagg = C/deg + bias ----
#pragma unroll
  for (int mf = 0; mf < 2; mf++) {
    int r0 = rbase + wm * 32 + mf * 16 + (lane >> 2);
    int r1 = r0 + 8;
    float id0 = (r0 < M) ? (1.0f / __ldg(&deg[r0])) : 0.f;
    float id1 = (r1 < M) ? (1.0f / __ldg(&deg[r1])) : 0.f;
#pragma unroll
    for (int ng = 0; ng < 4; ng++) {
#pragma unroll
      for (int nf = 0; nf < 2; nf++) {
        float* d = acc[mf][ng * 2 + nf];
        int col = wn * 64 + ng * 16 + nf * 8 + (lane & 3) * 2;
        float b0 = __ldg(&bias[col]);
        float b1 = __ldg(&bias[col + 1]);
        if (r0 < M) {
          size_t o = (size_t)r0 * HID + col;
          *reinterpret_cast<float2*>(C + o) = make_float2(d[0], d[1]);
          *reinterpret_cast<float2*>(Cagg + o) =
              make_float2(d[0] * id0 + b0, d[1] * id0 + b1);
        }
        if (r1 < M) {
          size_t o = (size_t)r1 * HID + col;
          *reinterpret_cast<float2*>(C + o) = make_float2(d[2], d[3]);
          *reinterpret_cast<float2*>(Cagg + o) =
              make_float2(d[2] * id1 + b0, d[3] * id1 + b1);
        }
      }
    }
  }
}

// ---------------- prep: weight split, x split ----------------
__global__ void wsplit_kernel(const float* __restrict__ W,
                              __nv_bfloat16* __restrict__ hi,
                              __nv_bfloat16* __restrict__ lo, int K, int N) {
  int idx = blockIdx.x * blockDim.x + threadIdx.x;
  if (idx < K * N) {
    int k = idx / N, n = idx % N;
    float v = W[idx];
    __nv_bfloat16 h = __float2bfloat16(v);
    hi[n * K + k] = h;
    lo[n * K + k] = __float2bfloat16(v - __bfloat162float(h));
  }
}

// x [M,K] fp32 -> ahi/alo bf16 (row-major, same layout)
__global__ __launch_bounds__(256) void xsplit_kernel(
    const float* __restrict__ x, __nv_bfloat16* __restrict__ hi,
    __nv_bfloat16* __restrict__ lo, size_t total4) {
  size_t idx = (size_t)blockIdx.x * blockDim.x + threadIdx.x;
  if (idx >= total4) return;
  float4 v = reinterpret_cast<const float4*>(x)[idx];
  uint2 uh, ul;
  split2(v.x, v.y, uh.x, ul.x);
  split2(v.z, v.w, uh.y, ul.y);
  reinterpret_cast<uint2*>(hi)[idx] = uh;
  reinterpret_cast<uint2*>(lo)[idx] = ul;
}

// ---------------- degree kernels ----------------
__global__ void deg_init_kernel(float* deg, int n) {
  int i = blockIdx.x * blockDim.x + threadIdx.x;
  if (i < n) deg[i] = 1.0f;
}
__global__ void deg_count_kernel(const int* __restrict__ dst, float* deg, int e) {
  int i = blockIdx.x * blockDim.x + threadIdx.x;
  if (i < e) atomicAdd(&deg[dst[i]], 1.0f);
}
__global__ void deg_fin_kernel(const float* __restrict__ deg, float* dinv, int n) {
  int i = blockIdx.x * blockDim.x + threadIdx.x;
  if (i < n) dinv[i] = rsqrtf(deg[i]);
}

// ---------------- aggregation: warp per edge, float4 gather + v4 RED ----------------
__global__ __launch_bounds__(256) void edge_scatter_v4_kernel(
    const int* __restrict__ src, const int* __restrict__ dst,
    const float* __restrict__ h, const float* __restrict__ dinv,
    float* __restrict__ agg, int e) {
  int ei = blockIdx.x * 8 + (threadIdx.x >> 5);
  if (ei >= e) return;
  int lane = threadIdx.x & 31;
  int s = __ldg(&src[ei]);
  int d = __ldg(&dst[ei]);
  float c = __ldg(&dinv[s]) * __ldg(&dinv[d]);
  const float4* hs = reinterpret_cast<const float4*>(h + (size_t)s * HID) + lane * 2;
  float4 a = __ldg(hs);
  float4 b = __ldg(hs + 1);
  float* base = agg + (size_t)d * HID + lane * 8;
  asm volatile("red.global.add.v4.f32 [%0], {%1,%2,%3,%4};" ::"l"(base),
               "f"(a.x * c), "f"(a.y * c), "f"(a.z * c), "f"(a.w * c) : "memory");
  asm volatile("red.global.add.v4.f32 [%0], {%1,%2,%3,%4};" ::"l"(base + 4),
               "f"(b.x * c), "f"(b.y * c), "f"(b.z * c), "f"(b.w * c) : "memory");
}

// ---------------- batchnorm + relu ----------------
__global__ void bn_zero_kernel(float* s, float* sq) {
  int t = threadIdx.x;
  if (t < HID) { s[t] = 0.f; sq[t] = 0.f; }
}

#define BN_RPB 256
__global__ __launch_bounds__(HID) void bn_partial_kernel(
    const float* __restrict__ h, float* s, float* sq, int n) {
  int col = threadIdx.x;
  int r0 = blockIdx.x * BN_RPB;
  int r1 = min(r0 + BN_RPB, n);
  float ps = 0.f, psq = 0.f;
  for (int r = r0; r < r1; r++) {
    float v = h[(size_t)r * HID + col];
    ps += v;
    psq += v * v;
  }
  atomicAdd(&s[col], ps);
  atomicAdd(&sq[col], psq);
}

__device__ __forceinline__ float4 bn_vec(const float* s, const float* sq,
                                         const float* gamma, const float* beta,
                                         int f, float4 v) {
  const float invN = 1.0f / (float)NNODES;
  float4 ss = *reinterpret_cast<const float4*>(s + f);
  float4 qq = *reinterpret_cast<const float4*>(sq + f);
  float4 gg = *reinterpret_cast<const float4*>(gamma + f);
  float4 bt = *reinterpret_cast<const float4*>(beta + f);
  float4 mu = make_float4(ss.x * invN, ss.y * invN, ss.z * invN, ss.w * invN);
  float4 o;
  o.x = fmaxf((v.x - mu.x) * gg.x * rsqrtf(qq.x * invN - mu.x * mu.x + BN_EPS) + bt.x, 0.f);
  o.y = fmaxf((v.y - mu.y) * gg.y * rsqrtf(qq.y * invN - mu.y * mu.y + BN_EPS) + bt.y, 0.f);
  o.z = fmaxf((v.z - mu.z) * gg.z * rsqrtf(qq.z * invN - mu.z * mu.z + BN_EPS) + bt.z, 0.f);
  o.w = fmaxf((v.w - mu.w) * gg.w * rsqrtf(qq.w * invN - mu.w * mu.w + BN_EPS) + bt.w, 0.f);
  return o;
}

// BN+ReLU, fp32 out (final layer)
__global__ __launch_bounds__(256) void bn_apply_relu_kernel(
    const float* __restrict__ h, const float* __restrict__ s,
    const float* __restrict__ sq, const float* __restrict__ gamma,
    const float* __restrict__ beta, float* __restrict__ out, int n) {
  size_t idx = (size_t)blockIdx.x * blockDim.x + threadIdx.x;
  size_t total = (size_t)n * (HID / 4);
  if (idx >= total) return;
  int f = (int)(idx & 63) * 4;
  float4 v = reinterpret_cast<const float4*>(h)[idx];
  reinterpret_cast<float4*>(out)[idx] = bn_vec(s, sq, gamma, beta, f, v);
}

// BN+ReLU, bf16 hi/lo split out (feeds next GEMM's A; [M,HID] layout)
__global__ __launch_bounds__(256) void bn_apply_relu_split_kernel(
    const float* __restrict__ h, const float* __restrict__ s,
    const float* __restrict__ sq, const float* __restrict__ gamma,
    const float* __restrict__ beta, __nv_bfloat16* __restrict__ ohi,
    __nv_bfloat16* __restrict__ olo, int n) {
  size_t idx = (size_t)blockIdx.x * blockDim.x + threadIdx.x;
  size_t total = (size_t)n * (HID / 4);
  if (idx >= total) return;
  int f = (int)(idx & 63) * 4;
  float4 v = reinterpret_cast<const float4*>(h)[idx];
  float4 o = bn_vec(s, sq, gamma, beta, f, v);
  uint2 uh, ul;
  split2(o.x, o.y, uh.x, ul.x);
  split2(o.z, o.w, uh.y, ul.y);
  reinterpret_cast<uint2*>(ohi)[idx] = uh;
  reinterpret_cast<uint2*>(olo)[idx] = ul;
}

// ---------------- launch ----------------
extern "C" void kernel_launch(void* const* d_in, const int* in_sizes, int n_in,
                              void* d_out, int out_size) {
  const float* x   = (const float*)d_in[0];
  const int*   ei  = (const int*)d_in[1];
  const float* W1  = (const float*)d_in[2];
  const float* b1  = (const float*)d_in[3];
  const float* g1  = (const float*)d_in[4];
  const float* be1 = (const float*)d_in[5];
  const float* W2  = (const float*)d_in[6];
  const float* b2  = (const float*)d_in[7];
  const float* g2  = (const float*)d_in[8];
  const float* be2 = (const float*)d_in[9];

  const int M = NNODES;
  const int E = in_sizes[1] / 2;
  const int* src = ei;
  const int* dst = ei + E;
  float* out = (float*)d_out;

  float *bufA, *bufB, *bufC, *deg, *dinv, *bsum, *bsumsq;
  __nv_bfloat16 *ahi, *alo, *w1hi, *w1lo, *w2hi, *w2lo;
  cudaGetSymbolAddress((void**)&bufA, g_bufA);
  cudaGetSymbolAddress((void**)&bufB, g_bufB);
  cudaGetSymbolAddress((void**)&bufC, g_bufC);
  cudaGetSymbolAddress((void**)&deg, g_deg);
  cudaGetSymbolAddress((void**)&dinv, g_dinv);
  cudaGetSymbolAddress((void**)&bsum, g_sum);
  cudaGetSymbolAddress((void**)&bsumsq, g_sumsq);
  cudaGetSymbolAddress((void**)&ahi, g_ahi);
  cudaGetSymbolAddress((void**)&alo, g_alo);
  cudaGetSymbolAddress((void**)&w1hi, g_w1hi);
  cudaGetSymbolAddress((void**)&w1lo, g_w1lo);
  cudaGetSymbolAddress((void**)&w2hi, g_w2hi);
  cudaGetSymbolAddress((void**)&w2lo, g_w2lo);

  cudaFuncSetAttribute(gemm_mma_kernel,
                       cudaFuncAttributeMaxDynamicSharedMemorySize, GEMM_SMEM);

  const int vecGrid = (int)(((size_t)M * (HID / 4) + 255) / 256);
  const int gemmGrid = (M + 127) / 128;
  const int bnGrid = (M + BN_RPB - 1) / BN_RPB;
  const int scatGrid = (E + 7) / 8;
  const size_t xTotal4 = (size_t)M * INDIM / 4;

  // prep: weight split, x split, degrees
  wsplit_kernel<<<(INDIM * HID + 255) / 256, 256>>>(W1, w1hi, w1lo, INDIM, HID);
  wsplit_kernel<<<(HID * HID + 255) / 256, 256>>>(W2, w2hi, w2lo, HID, HID);
  xsplit_kernel<<<(int)((xTotal4 + 255) / 256), 256>>>(x, ahi, alo, xTotal4);
  deg_init_kernel<<<(M + 255) / 256, 256>>>(deg, M);
  deg_count_kernel<<<(E + 255) / 256, 256>>>(dst, deg, E);
  deg_fin_kernel<<<(M + 255) / 256, 256>>>(deg, dinv, M);

  // ---- layer 1 ----
  gemm_mma_kernel<<<gemmGrid, 512, GEMM_SMEM>>>(M, INDIM, ahi, alo, w1hi, w1lo,
                                                deg, b1, bufA, bufB);
  edge_scatter_v4_kernel<<<scatGrid, 256>>>(src, dst, bufA, dinv, bufB, E);
  bn_zero_kernel<<<1, HID>>>(bsum, bsumsq);
  bn_partial_kernel<<<bnGrid, HID>>>(bufB, bsum, bsumsq, M);
  bn_apply_relu_split_kernel<<<vecGrid, 256>>>(bufB, bsum, bsumsq, g1, be1,
                                               ahi, alo, M);

  // ---- layer 2 ----
  gemm_mma_kernel<<<gemmGrid, 512, GEMM_SMEM>>>(M, HID, ahi, alo, w2hi, w2lo,
                                                deg, b2, bufC, out);
  edge_scatter_v4_kernel<<<scatGrid, 256>>>(src, dst, bufC, dinv, out, E);
  bn_zero_kernel<<<1, HID>>>(bsum, bsumsq);
  bn_partial_kernel<<<bnGrid, HID>>>(out, bsum, bsumsq, M);
  bn_apply_relu_kernel<<<vecGrid, 256>>>(out, bsum, bsumsq, g2, be2, out, M);
}